// round 12
// baseline (speedup 1.0000x reference)
#include <cuda_runtime.h>
#include <cuda_fp16.h>
#include <math.h>

#define BATCH   256
#define JN      10
#define ICAPS   1152
#define DN      16
#define JD      160          // JN*DN
#define BJD     (BATCH*JD)   // 40960
#define BT      32           // b per pass CTA
#define IT      32           // i per pass CTA
#define IB      8            // i batch (sync cadence)
#define NP      (ICAPS/IT)   // 36 partial slices

// -------- scratch ------------------------------------------------------
// u_hat layout: [j][i][b][16 x half]  (32B per (j,i,b) entry)
__device__ __align__(1024) __half g_uhat[(size_t)JN * ICAPS * BATCH * DN]; // ~94.4MB
__device__ float g_acc[2 * BJD];                 // [0]=s0raw, [1]=s1
__device__ float g_part[(size_t)NP * BJD];       // ~5.9 MB

// -------- f32x2 helpers (k_uhat) ----------------------------------------
typedef unsigned long long u64t;
__device__ __forceinline__ u64t pack2(float x, float y) {
    u64t r; asm("mov.b64 %0, {%1, %2};" : "=l"(r) : "f"(x), "f"(y)); return r;
}
__device__ __forceinline__ void unpack2(u64t v, float& x, float& y) {
    asm("mov.b64 {%0, %1}, %2;" : "=f"(x), "=f"(y) : "l"(v));
}
__device__ __forceinline__ u64t fma2(u64t a, u64t b, u64t c) {
    u64t d; asm("fma.rn.f32x2 %0, %1, %2, %3;" : "=l"(d) : "l"(a), "l"(b), "l"(c));
    return d;
}
__device__ __forceinline__ u64t addf2(u64t a, u64t b) {
    u64t d; asm("add.rn.f32x2 %0, %1, %2;" : "=l"(d) : "l"(a), "l"(b)); return d;
}

// -------- K1: u_hat = W @ x (fp16, [j][i][b] layout), fused partial s0 ---
// (byte-identical to the R6/R11 version)
__global__ __launch_bounds__(320, 2) void k_uhat(const float* __restrict__ x,
                                                 const float* __restrict__ W) {
    __shared__ __align__(16) float xs[16 * 4 * 32 * 4];   // 32 KB interleaved x
    const int i0 = blockIdx.x * 16;
    const int b0 = blockIdx.y * 64;
    const int t  = threadIdx.x;

    const float4* xg = (const float4*)x;   // [256][1152][8] -> 2304 f4 per b
    for (int f = t; f < 2048; f += 320) {
        int b = f >> 5, q = f & 31;            // q = ii*2 + qe
        float4 v = xg[(size_t)(b0 + b) * 2304 + (size_t)i0 * 2 + q];
        int ii = q >> 1, qe = q & 1;
        int b2 = b >> 1, bl = b & 1;
        float* p = xs + (ii * 128 + qe * 64 + b2) * 4 + bl;
        p[0] = v.x; p[2] = v.y; p[128] = v.z; p[130] = v.w;
    }
    __syncthreads();

    const int jd2 = t % 80;          // j*8 + dp  (d0 = 2*dp)
    const int seg = t / 80;
    const int j   = jd2 >> 3, dp = jd2 & 7;
    const float4* Wg = (const float4*)W + (size_t)j * 36864 + dp * 4;
    __half2* uh2 = (__half2*)g_uhat;
    const ulonglong2* xq2base = (const ulonglong2*)xs;

    for (int bt = 0; bt < 2; bt++) {
        const int b2base = seg * 8 + bt * 4;
        u64t s0a[4] = {0,0,0,0};
        u64t s1a[4] = {0,0,0,0};
        for (int ii = 0; ii < 16; ii++) {
            const int i = i0 + ii;
            const float4 w00 = Wg[(size_t)i * 32];
            const float4 w01 = Wg[(size_t)i * 32 + 1];
            const float4 w10 = Wg[(size_t)i * 32 + 2];
            const float4 w11 = Wg[(size_t)i * 32 + 3];
            u64t wd0[8], wd1[8];
            wd0[0]=pack2(w00.x,w00.x); wd0[1]=pack2(w00.y,w00.y);
            wd0[2]=pack2(w00.z,w00.z); wd0[3]=pack2(w00.w,w00.w);
            wd0[4]=pack2(w01.x,w01.x); wd0[5]=pack2(w01.y,w01.y);
            wd0[6]=pack2(w01.z,w01.z); wd0[7]=pack2(w01.w,w01.w);
            wd1[0]=pack2(w10.x,w10.x); wd1[1]=pack2(w10.y,w10.y);
            wd1[2]=pack2(w10.z,w10.z); wd1[3]=pack2(w10.w,w10.w);
            wd1[4]=pack2(w11.x,w11.x); wd1[5]=pack2(w11.y,w11.y);
            wd1[6]=pack2(w11.z,w11.z); wd1[7]=pack2(w11.w,w11.w);
            const ulonglong2* xq2 = xq2base + ii * 128;
            const size_t obase = ((size_t)j * ICAPS + i) * BATCH;
            #pragma unroll
            for (int bp = 0; bp < 4; bp++) {
                const int b2 = b2base + bp;
                u64t a0 = 0, a1 = 0;
                #pragma unroll
                for (int e2 = 0; e2 < 4; e2++) {
                    ulonglong2 xv = xq2[e2 * 32 + b2];
                    a0 = fma2(wd0[2*e2],   xv.x, a0);
                    a0 = fma2(wd0[2*e2+1], xv.y, a0);
                    a1 = fma2(wd1[2*e2],   xv.x, a1);
                    a1 = fma2(wd1[2*e2+1], xv.y, a1);
                }
                float u00,u01,u10,u11;
                unpack2(a0, u00, u01);   // d0   : b_even, b_odd
                unpack2(a1, u10, u11);   // d0+1 : b_even, b_odd
                const int bg = b0 + 2*b2;
                uh2[(obase + bg)     * 8 + dp] = __floats2half2_rn(u00, u10);
                uh2[(obase + bg + 1) * 8 + dp] = __floats2half2_rn(u01, u11);
                s0a[bp] = addf2(s0a[bp], a0);
                s1a[bp] = addf2(s1a[bp], a1);
            }
        }
        #pragma unroll
        for (int bp = 0; bp < 4; bp++) {
            float p0,p1,q0,q1;
            unpack2(s0a[bp], p0, p1);
            unpack2(s1a[bp], q0, q1);
            float* sb = &g_acc[(b0 + 2*(b2base+bp)) * JD + jd2 * 2];
            atomicAdd(sb,           p0);
            atomicAdd(sb + 1,       q0);
            atomicAdd(sb + JD,      p1);
            atomicAdd(sb + JD + 1,  q1);
        }
    }
}

// -------- k_pass: routing pass, RCP-deduplicated softmax ----------------
// grid (36, 8), block (32 b, 10 j). Warp j=0 computes the per-(b,i)
// reciprocal ONCE (10x fewer MUFU.RCP); others consume it from smem.
__global__ __launch_bounds__(320, 3) void k_pass(int round) {
    __shared__ float se[2][IB][JN][BT];    // e-values, 20 KB
    __shared__ float sinv[2][IB][BT];      // 1/sum per (k, lane), 2 KB

    const int lane = threadIdx.x;          // b within tile
    const int j    = threadIdx.y;
    const int b    = blockIdx.y * BT + lane;
    const int i0   = blockIdx.x * IT;

    // ---- vs[j,:] = v0 (+ v1) in registers ----
    float vs[DN];
    {
        float tmp[DN]; float sq = 0.f;
        const float* a0 = g_acc + b * JD + j * DN;
        #pragma unroll
        for (int d = 0; d < DN; d++) { tmp[d] = 0.1f * a0[d]; sq += tmp[d]*tmp[d]; }
        float sc = (sq / (1.0f + sq)) * rsqrtf(sq + 1e-7f);
        #pragma unroll
        for (int d = 0; d < DN; d++) vs[d] = tmp[d] * sc;
        if (round == 2) {
            const float* a1 = g_acc + BJD + b * JD + j * DN;
            sq = 0.f;
            #pragma unroll
            for (int d = 0; d < DN; d++) { tmp[d] = a1[d]; sq += tmp[d]*tmp[d]; }
            sc = (sq / (1.0f + sq)) * rsqrtf(sq + 1e-7f);
            #pragma unroll
            for (int d = 0; d < DN; d++) vs[d] += tmp[d] * sc;
        }
    }

    const uint4* ug = (const uint4*)g_uhat;
    // entry (j,i,b) occupies 32B = 2 uint4; uint4 index = 2*entry
    const size_t e0 = (((size_t)j * ICAPS + i0) * BATCH + b) * 2;

    float s[DN];
    #pragma unroll
    for (int d = 0; d < DN; d++) s[d] = 0.f;

    int buf = 0;
    for (int t0 = 0; t0 < IT; t0 += IB) {
        // ---- phase A: loads, dot, exp, publish e ----
        float ev[IB];
        #pragma unroll
        for (int k = 0; k < IB; k++) {
            const size_t ix = e0 + (size_t)(t0 + k) * (2 * BATCH);
            uint4 lo = ug[ix];
            uint4 hi = ug[ix + 1];
            const __half2* h0 = (const __half2*)&lo;
            const __half2* h1 = (const __half2*)&hi;
            float a = 0.f;
            #pragma unroll
            for (int d2 = 0; d2 < 4; d2++) {
                float2 f0 = __half22float2(h0[d2]);
                a = fmaf(f0.x, vs[2*d2],     a);
                a = fmaf(f0.y, vs[2*d2 + 1], a);
                float2 f1 = __half22float2(h1[d2]);
                a = fmaf(f1.x, vs[8 + 2*d2], a);
                a = fmaf(f1.y, vs[9 + 2*d2], a);
            }
            ev[k] = __expf(a);
            se[buf][k][j][lane] = ev[k];
        }
        __syncthreads();

        // ---- warp j=0: one reciprocal per (b,i) ----
        if (j == 0) {
            #pragma unroll
            for (int k = 0; k < IB; k++) {
                float sum = 0.f;
                #pragma unroll
                for (int jj = 0; jj < JN; jj++) sum += se[buf][k][jj][lane];
                sinv[buf][k][lane] = __fdividef(1.0f, sum);
            }
        }
        __syncthreads();

        // ---- phase B: c = ev * inv, accumulate (reload = L1 hit) ----
        #pragma unroll
        for (int k = 0; k < IB; k++) {
            float c = ev[k] * sinv[buf][k][lane];
            const size_t ix = e0 + (size_t)(t0 + k) * (2 * BATCH);
            uint4 lo = ug[ix];
            uint4 hi = ug[ix + 1];
            const __half2* h0 = (const __half2*)&lo;
            const __half2* h1 = (const __half2*)&hi;
            #pragma unroll
            for (int d2 = 0; d2 < 4; d2++) {
                float2 f0 = __half22float2(h0[d2]);
                s[2*d2]     = fmaf(f0.x, c, s[2*d2]);
                s[2*d2 + 1] = fmaf(f0.y, c, s[2*d2 + 1]);
                float2 f1 = __half22float2(h1[d2]);
                s[8 + 2*d2] = fmaf(f1.x, c, s[8 + 2*d2]);
                s[9 + 2*d2] = fmaf(f1.y, c, s[9 + 2*d2]);
            }
        }
        buf ^= 1;
    }

    // ---- write per-CTA partial (coalesced float4 stores) ----
    float* dst = g_part + (size_t)blockIdx.x * BJD + (size_t)b * JD + j * DN;
    #pragma unroll
    for (int q = 0; q < 4; q++)
        ((float4*)dst)[q] = make_float4(s[4*q], s[4*q+1], s[4*q+2], s[4*q+3]);
}

// -------- k_reduce: s1 = sum of NP partial slices (float4) ---------------
__global__ void k_reduce() {
    const int idx = blockIdx.x * 256 + threadIdx.x;   // < BJD/4
    const float4* p4 = (const float4*)g_part;
    float4 s = make_float4(0.f, 0.f, 0.f, 0.f);
    #pragma unroll 4
    for (int p = 0; p < NP; p++) {
        float4 v = p4[(size_t)p * (BJD / 4) + idx];
        s.x += v.x; s.y += v.y; s.z += v.z; s.w += v.w;
    }
    ((float4*)g_acc)[BJD / 4 + idx] = s;
}

// -------- k_final: out = squash(sum of partials), float4 -----------------
__global__ __launch_bounds__(256) void k_final(float* __restrict__ out) {
    const int idx = blockIdx.x * 256 + threadIdx.x;   // < BJD/4 (4 jd each)
    const float4* p4 = (const float4*)g_part;
    float4 v = make_float4(0.f, 0.f, 0.f, 0.f);
    #pragma unroll 4
    for (int p = 0; p < NP; p++) {
        float4 t = p4[(size_t)p * (BJD / 4) + idx];
        v.x += t.x; v.y += t.y; v.z += t.z; v.w += t.w;
    }
    // 4 consecutive lanes cover one (b,j)'s 16 d's
    float sq = v.x*v.x + v.y*v.y + v.z*v.z + v.w*v.w;
    sq += __shfl_xor_sync(0xffffffff, sq, 1);
    sq += __shfl_xor_sync(0xffffffff, sq, 2);
    float sc = (sq / (1.0f + sq)) * rsqrtf(sq + 1e-7f);
    v.x *= sc; v.y *= sc; v.z *= sc; v.w *= sc;
    ((float4*)out)[idx] = v;
}

// -------- launch --------------------------------------------------------
extern "C" void kernel_launch(void* const* d_in, const int* in_sizes, int n_in,
                              void* d_out, int out_size) {
    const float* x = (const float*)d_in[0];   // [256,1152,8]
    const float* W = (const float*)d_in[1];   // [10,1152,16,8]
    float* out = (float*)d_out;               // [256,10,16]

    void* acc_ptr = nullptr;
    cudaGetSymbolAddress(&acc_ptr, g_acc);
    cudaMemsetAsync(acc_ptr, 0, BJD * sizeof(float));   // s0 only

    k_uhat<<<dim3(ICAPS / 16, BATCH / 64), 320>>>(x, W);
    k_pass<<<dim3(NP, BATCH / BT), dim3(BT, JN)>>>(1);
    k_reduce<<<BJD / 4 / 256, 256>>>();
    k_pass<<<dim3(NP, BATCH / BT), dim3(BT, JN)>>>(2);
    k_final<<<BJD / 4 / 256, 256>>>(out);
}

// round 13
// speedup vs baseline: 1.0418x; 1.0418x over previous
#include <cuda_runtime.h>
#include <cuda_fp16.h>
#include <math.h>

#define BATCH   256
#define JN      10
#define ICAPS   1152
#define DN      16
#define JD      160          // JN*DN
#define BJD     (BATCH*JD)   // 40960
#define BT      32           // b per pass CTA
#define IT      32           // i per pass CTA
#define IB      8            // i batch (sync cadence)
#define NP      (ICAPS/IT)   // 36 partial slices

// -------- scratch ------------------------------------------------------
// u_hat layout: [j][i][b][16 x half]  (32B per (j,i,b) entry)
__device__ __align__(1024) __half g_uhat[(size_t)JN * ICAPS * BATCH * DN]; // ~94.4MB
__device__ float g_acc[2 * BJD];                 // [0]=s0raw, [1]=s1
__device__ float g_part[(size_t)NP * BJD];       // ~5.9 MB

// -------- f32x2 helpers (k_uhat) ----------------------------------------
typedef unsigned long long u64t;
__device__ __forceinline__ u64t pack2(float x, float y) {
    u64t r; asm("mov.b64 %0, {%1, %2};" : "=l"(r) : "f"(x), "f"(y)); return r;
}
__device__ __forceinline__ void unpack2(u64t v, float& x, float& y) {
    asm("mov.b64 {%0, %1}, %2;" : "=f"(x), "=f"(y) : "l"(v));
}
__device__ __forceinline__ u64t fma2(u64t a, u64t b, u64t c) {
    u64t d; asm("fma.rn.f32x2 %0, %1, %2, %3;" : "=l"(d) : "l"(a), "l"(b), "l"(c));
    return d;
}
__device__ __forceinline__ u64t addf2(u64t a, u64t b) {
    u64t d; asm("add.rn.f32x2 %0, %1, %2;" : "=l"(d) : "l"(a), "l"(b)); return d;
}

// -------- MUFU-free exp / reciprocal (FMA+ALU pipes only) ---------------
// e^a = 2^(a*log2e); |a| < 30. Taylor deg-4 for 2^f on [-0.5, 0.5],
// rel err ~4e-5. Exponent assembled via integer add into the float bits.
__device__ __forceinline__ float fexp(float a) {
    float t = a * 1.44269504f;
    float m = t + 12582912.0f;                        // rn-to-int in mantissa
    int  ki = __float_as_int(m) - 0x4B400000;         // k = round(t)
    float f = t - (m - 12582912.0f);                  // f in [-0.5, 0.5]
    float p =             9.61812910e-3f;
    p = fmaf(p, f, 5.55041087e-2f);
    p = fmaf(p, f, 2.40226507e-1f);
    p = fmaf(p, f, 6.93147181e-1f);
    p = fmaf(p, f, 1.0f);
    return __int_as_float(__float_as_int(p) + (ki << 23));
}
// 1/x for x>0 via bit-trick estimate + 2 Newton steps; rel err ~6e-6.
__device__ __forceinline__ float frcp(float x) {
    float r = __int_as_float(0x7EF311C3 - __float_as_int(x));
    r = r * fmaf(-x, r, 2.0f);
    r = r * fmaf(-x, r, 2.0f);
    return r;
}

// -------- K1: u_hat = W @ x (fp16, [j][i][b] layout), fused partial s0 ---
// (byte-identical to the R6/R11 version)
__global__ __launch_bounds__(320, 2) void k_uhat(const float* __restrict__ x,
                                                 const float* __restrict__ W) {
    __shared__ __align__(16) float xs[16 * 4 * 32 * 4];   // 32 KB interleaved x
    const int i0 = blockIdx.x * 16;
    const int b0 = blockIdx.y * 64;
    const int t  = threadIdx.x;

    const float4* xg = (const float4*)x;   // [256][1152][8] -> 2304 f4 per b
    for (int f = t; f < 2048; f += 320) {
        int b = f >> 5, q = f & 31;            // q = ii*2 + qe
        float4 v = xg[(size_t)(b0 + b) * 2304 + (size_t)i0 * 2 + q];
        int ii = q >> 1, qe = q & 1;
        int b2 = b >> 1, bl = b & 1;
        float* p = xs + (ii * 128 + qe * 64 + b2) * 4 + bl;
        p[0] = v.x; p[2] = v.y; p[128] = v.z; p[130] = v.w;
    }
    __syncthreads();

    const int jd2 = t % 80;          // j*8 + dp  (d0 = 2*dp)
    const int seg = t / 80;
    const int j   = jd2 >> 3, dp = jd2 & 7;
    const float4* Wg = (const float4*)W + (size_t)j * 36864 + dp * 4;
    __half2* uh2 = (__half2*)g_uhat;
    const ulonglong2* xq2base = (const ulonglong2*)xs;

    for (int bt = 0; bt < 2; bt++) {
        const int b2base = seg * 8 + bt * 4;
        u64t s0a[4] = {0,0,0,0};
        u64t s1a[4] = {0,0,0,0};
        for (int ii = 0; ii < 16; ii++) {
            const int i = i0 + ii;
            const float4 w00 = Wg[(size_t)i * 32];
            const float4 w01 = Wg[(size_t)i * 32 + 1];
            const float4 w10 = Wg[(size_t)i * 32 + 2];
            const float4 w11 = Wg[(size_t)i * 32 + 3];
            u64t wd0[8], wd1[8];
            wd0[0]=pack2(w00.x,w00.x); wd0[1]=pack2(w00.y,w00.y);
            wd0[2]=pack2(w00.z,w00.z); wd0[3]=pack2(w00.w,w00.w);
            wd0[4]=pack2(w01.x,w01.x); wd0[5]=pack2(w01.y,w01.y);
            wd0[6]=pack2(w01.z,w01.z); wd0[7]=pack2(w01.w,w01.w);
            wd1[0]=pack2(w10.x,w10.x); wd1[1]=pack2(w10.y,w10.y);
            wd1[2]=pack2(w10.z,w10.z); wd1[3]=pack2(w10.w,w10.w);
            wd1[4]=pack2(w11.x,w11.x); wd1[5]=pack2(w11.y,w11.y);
            wd1[6]=pack2(w11.z,w11.z); wd1[7]=pack2(w11.w,w11.w);
            const ulonglong2* xq2 = xq2base + ii * 128;
            const size_t obase = ((size_t)j * ICAPS + i) * BATCH;
            #pragma unroll
            for (int bp = 0; bp < 4; bp++) {
                const int b2 = b2base + bp;
                u64t a0 = 0, a1 = 0;
                #pragma unroll
                for (int e2 = 0; e2 < 4; e2++) {
                    ulonglong2 xv = xq2[e2 * 32 + b2];
                    a0 = fma2(wd0[2*e2],   xv.x, a0);
                    a0 = fma2(wd0[2*e2+1], xv.y, a0);
                    a1 = fma2(wd1[2*e2],   xv.x, a1);
                    a1 = fma2(wd1[2*e2+1], xv.y, a1);
                }
                float u00,u01,u10,u11;
                unpack2(a0, u00, u01);   // d0   : b_even, b_odd
                unpack2(a1, u10, u11);   // d0+1 : b_even, b_odd
                const int bg = b0 + 2*b2;
                uh2[(obase + bg)     * 8 + dp] = __floats2half2_rn(u00, u10);
                uh2[(obase + bg + 1) * 8 + dp] = __floats2half2_rn(u01, u11);
                s0a[bp] = addf2(s0a[bp], a0);
                s1a[bp] = addf2(s1a[bp], a1);
            }
        }
        #pragma unroll
        for (int bp = 0; bp < 4; bp++) {
            float p0,p1,q0,q1;
            unpack2(s0a[bp], p0, p1);
            unpack2(s1a[bp], q0, q1);
            float* sb = &g_acc[(b0 + 2*(b2base+bp)) * JD + jd2 * 2];
            atomicAdd(sb,           p0);
            atomicAdd(sb + 1,       q0);
            atomicAdd(sb + JD,      p1);
            atomicAdd(sb + JD + 1,  q1);
        }
    }
}

// -------- k_pass: routing pass, MUFU-free exp/div -----------------------
// grid (36, 8), block (32 b, 10 j). Identical structure to the R11 136us
// version; only __expf -> fexp, __fdividef -> ev * frcp(sum).
__global__ __launch_bounds__(320, 3) void k_pass(int round) {
    __shared__ float se[2][IB][JN][BT];   // e-values, 20 KB

    const int lane = threadIdx.x;          // b within tile
    const int j    = threadIdx.y;
    const int b    = blockIdx.y * BT + lane;
    const int i0   = blockIdx.x * IT;

    // ---- vs[j,:] = v0 (+ v1) in registers ----
    float vs[DN];
    {
        float tmp[DN]; float sq = 0.f;
        const float* a0 = g_acc + b * JD + j * DN;
        #pragma unroll
        for (int d = 0; d < DN; d++) { tmp[d] = 0.1f * a0[d]; sq += tmp[d]*tmp[d]; }
        float sc = (sq / (1.0f + sq)) * rsqrtf(sq + 1e-7f);
        #pragma unroll
        for (int d = 0; d < DN; d++) vs[d] = tmp[d] * sc;
        if (round == 2) {
            const float* a1 = g_acc + BJD + b * JD + j * DN;
            sq = 0.f;
            #pragma unroll
            for (int d = 0; d < DN; d++) { tmp[d] = a1[d]; sq += tmp[d]*tmp[d]; }
            sc = (sq / (1.0f + sq)) * rsqrtf(sq + 1e-7f);
            #pragma unroll
            for (int d = 0; d < DN; d++) vs[d] += tmp[d] * sc;
        }
    }

    const uint4* ug = (const uint4*)g_uhat;
    // entry (j,i,b) occupies 32B = 2 uint4; uint4 index = 2*entry
    const size_t e0 = (((size_t)j * ICAPS + i0) * BATCH + b) * 2;

    float s[DN];
    #pragma unroll
    for (int d = 0; d < DN; d++) s[d] = 0.f;

    int buf = 0;
    for (int t0 = 0; t0 < IT; t0 += IB) {
        // ---- phase A: loads, dot, exp (FMA pipe), publish e ----
        float ev[IB];
        #pragma unroll
        for (int k = 0; k < IB; k++) {
            const size_t ix = e0 + (size_t)(t0 + k) * (2 * BATCH);
            uint4 lo = ug[ix];
            uint4 hi = ug[ix + 1];
            const __half2* h0 = (const __half2*)&lo;
            const __half2* h1 = (const __half2*)&hi;
            float a = 0.f;
            #pragma unroll
            for (int d2 = 0; d2 < 4; d2++) {
                float2 f0 = __half22float2(h0[d2]);
                a = fmaf(f0.x, vs[2*d2],     a);
                a = fmaf(f0.y, vs[2*d2 + 1], a);
                float2 f1 = __half22float2(h1[d2]);
                a = fmaf(f1.x, vs[8 + 2*d2], a);
                a = fmaf(f1.y, vs[9 + 2*d2], a);
            }
            ev[k] = fexp(a);
            se[buf][k][j][lane] = ev[k];
        }
        __syncthreads();
        // ---- phase B: normalize via frcp, accumulate (reload = L1 hit) --
        #pragma unroll
        for (int k = 0; k < IB; k++) {
            float sum = 0.f;
            #pragma unroll
            for (int jj = 0; jj < JN; jj++) sum += se[buf][k][jj][lane];
            float c = ev[k] * frcp(sum);
            const size_t ix = e0 + (size_t)(t0 + k) * (2 * BATCH);
            uint4 lo = ug[ix];
            uint4 hi = ug[ix + 1];
            const __half2* h0 = (const __half2*)&lo;
            const __half2* h1 = (const __half2*)&hi;
            #pragma unroll
            for (int d2 = 0; d2 < 4; d2++) {
                float2 f0 = __half22float2(h0[d2]);
                s[2*d2]     = fmaf(f0.x, c, s[2*d2]);
                s[2*d2 + 1] = fmaf(f0.y, c, s[2*d2 + 1]);
                float2 f1 = __half22float2(h1[d2]);
                s[8 + 2*d2] = fmaf(f1.x, c, s[8 + 2*d2]);
                s[9 + 2*d2] = fmaf(f1.y, c, s[9 + 2*d2]);
            }
        }
        buf ^= 1;
    }

    // ---- write per-CTA partial (coalesced float4 stores) ----
    float* dst = g_part + (size_t)blockIdx.x * BJD + (size_t)b * JD + j * DN;
    #pragma unroll
    for (int q = 0; q < 4; q++)
        ((float4*)dst)[q] = make_float4(s[4*q], s[4*q+1], s[4*q+2], s[4*q+3]);
}

// -------- k_reduce: s1 = sum of NP partial slices (float4) ---------------
__global__ void k_reduce() {
    const int idx = blockIdx.x * 256 + threadIdx.x;   // < BJD/4
    const float4* p4 = (const float4*)g_part;
    float4 s = make_float4(0.f, 0.f, 0.f, 0.f);
    #pragma unroll 4
    for (int p = 0; p < NP; p++) {
        float4 v = p4[(size_t)p * (BJD / 4) + idx];
        s.x += v.x; s.y += v.y; s.z += v.z; s.w += v.w;
    }
    ((float4*)g_acc)[BJD / 4 + idx] = s;
}

// -------- k_final: out = squash(sum of partials), float4 -----------------
__global__ __launch_bounds__(256) void k_final(float* __restrict__ out) {
    const int idx = blockIdx.x * 256 + threadIdx.x;   // < BJD/4 (4 jd each)
    const float4* p4 = (const float4*)g_part;
    float4 v = make_float4(0.f, 0.f, 0.f, 0.f);
    #pragma unroll 4
    for (int p = 0; p < NP; p++) {
        float4 t = p4[(size_t)p * (BJD / 4) + idx];
        v.x += t.x; v.y += t.y; v.z += t.z; v.w += t.w;
    }
    // 4 consecutive lanes cover one (b,j)'s 16 d's
    float sq = v.x*v.x + v.y*v.y + v.z*v.z + v.w*v.w;
    sq += __shfl_xor_sync(0xffffffff, sq, 1);
    sq += __shfl_xor_sync(0xffffffff, sq, 2);
    float sc = (sq / (1.0f + sq)) * rsqrtf(sq + 1e-7f);
    v.x *= sc; v.y *= sc; v.z *= sc; v.w *= sc;
    ((float4*)out)[idx] = v;
}

// -------- launch --------------------------------------------------------
extern "C" void kernel_launch(void* const* d_in, const int* in_sizes, int n_in,
                              void* d_out, int out_size) {
    const float* x = (const float*)d_in[0];   // [256,1152,8]
    const float* W = (const float*)d_in[1];   // [10,1152,16,8]
    float* out = (float*)d_out;               // [256,10,16]

    void* acc_ptr = nullptr;
    cudaGetSymbolAddress(&acc_ptr, g_acc);
    cudaMemsetAsync(acc_ptr, 0, BJD * sizeof(float));   // s0 only

    k_uhat<<<dim3(ICAPS / 16, BATCH / 64), 320>>>(x, W);
    k_pass<<<dim3(NP, BATCH / BT), dim3(BT, JN)>>>(1);
    k_reduce<<<BJD / 4 / 256, 256>>>();
    k_pass<<<dim3(NP, BATCH / BT), dim3(BT, JN)>>>(2);
    k_final<<<BJD / 4 / 256, 256>>>(out);
}

// round 14
// speedup vs baseline: 1.3166x; 1.2637x over previous
#include <cuda_runtime.h>
#include <cuda_fp16.h>
#include <math.h>

#define BATCH   256
#define JN      10
#define ICAPS   1152
#define DN      16
#define JD      160          // JN*DN
#define BJD     (BATCH*JD)   // 40960
#define IT      32           // i per pass warp
#define NP      (ICAPS/IT)   // 36 partial slices
#define GW      4            // warps per pass CTA

// -------- scratch ------------------------------------------------------
// u_hat layout: [i][b][j][d] halves (32B per (i,b,j) entry; i outermost)
__device__ __align__(1024) __half g_uhat[(size_t)ICAPS * BATCH * JD]; // ~94.4MB
__device__ float g_acc[2 * BJD];                 // [0]=s0raw, [1]=s1
__device__ float g_part[(size_t)NP * BJD];       // ~5.9 MB

// -------- f32x2 helpers (k_uhat) ----------------------------------------
typedef unsigned long long u64t;
__device__ __forceinline__ u64t pack2(float x, float y) {
    u64t r; asm("mov.b64 %0, {%1, %2};" : "=l"(r) : "f"(x), "f"(y)); return r;
}
__device__ __forceinline__ void unpack2(u64t v, float& x, float& y) {
    asm("mov.b64 {%0, %1}, %2;" : "=f"(x), "=f"(y) : "l"(v));
}
__device__ __forceinline__ u64t fma2(u64t a, u64t b, u64t c) {
    u64t d; asm("fma.rn.f32x2 %0, %1, %2, %3;" : "=l"(d) : "l"(a), "l"(b), "l"(c));
    return d;
}
__device__ __forceinline__ u64t addf2(u64t a, u64t b) {
    u64t d; asm("add.rn.f32x2 %0, %1, %2;" : "=l"(d) : "l"(a), "l"(b)); return d;
}

// -------- MUFU-free exp / reciprocal (FMA+ALU pipes) ---------------------
__device__ __forceinline__ float fexp(float a) {
    float t = a * 1.44269504f;
    float m = t + 12582912.0f;
    int  ki = __float_as_int(m) - 0x4B400000;
    float f = t - (m - 12582912.0f);
    float p =             9.61812910e-3f;
    p = fmaf(p, f, 5.55041087e-2f);
    p = fmaf(p, f, 2.40226507e-1f);
    p = fmaf(p, f, 6.93147181e-1f);
    p = fmaf(p, f, 1.0f);
    return __int_as_float(__float_as_int(p) + (ki << 23));
}
__device__ __forceinline__ float frcp(float x) {
    float r = __int_as_float(0x7EF311C3 - __float_as_int(x));
    r = r * fmaf(-x, r, 2.0f);
    r = r * fmaf(-x, r, 2.0f);
    return r;
}

// -------- K1: u_hat = W @ x (fp16, [i][b][jd] layout), fused partial s0 --
// Identical compute to R6/R11; only the two store addresses changed.
__global__ __launch_bounds__(320, 2) void k_uhat(const float* __restrict__ x,
                                                 const float* __restrict__ W) {
    __shared__ __align__(16) float xs[16 * 4 * 32 * 4];   // 32 KB interleaved x
    const int i0 = blockIdx.x * 16;
    const int b0 = blockIdx.y * 64;
    const int t  = threadIdx.x;

    const float4* xg = (const float4*)x;   // [256][1152][8] -> 2304 f4 per b
    for (int f = t; f < 2048; f += 320) {
        int b = f >> 5, q = f & 31;            // q = ii*2 + qe
        float4 v = xg[(size_t)(b0 + b) * 2304 + (size_t)i0 * 2 + q];
        int ii = q >> 1, qe = q & 1;
        int b2 = b >> 1, bl = b & 1;
        float* p = xs + (ii * 128 + qe * 64 + b2) * 4 + bl;
        p[0] = v.x; p[2] = v.y; p[128] = v.z; p[130] = v.w;
    }
    __syncthreads();

    const int jd2 = t % 80;          // j*8 + dp  (d0 = 2*dp)
    const int seg = t / 80;
    const int j   = jd2 >> 3, dp = jd2 & 7;
    const float4* Wg = (const float4*)W + (size_t)j * 36864 + dp * 4;
    __half2* uh2 = (__half2*)g_uhat;
    const ulonglong2* xq2base = (const ulonglong2*)xs;

    for (int bt = 0; bt < 2; bt++) {
        const int b2base = seg * 8 + bt * 4;
        u64t s0a[4] = {0,0,0,0};
        u64t s1a[4] = {0,0,0,0};
        for (int ii = 0; ii < 16; ii++) {
            const int i = i0 + ii;
            const float4 w00 = Wg[(size_t)i * 32];
            const float4 w01 = Wg[(size_t)i * 32 + 1];
            const float4 w10 = Wg[(size_t)i * 32 + 2];
            const float4 w11 = Wg[(size_t)i * 32 + 3];
            u64t wd0[8], wd1[8];
            wd0[0]=pack2(w00.x,w00.x); wd0[1]=pack2(w00.y,w00.y);
            wd0[2]=pack2(w00.z,w00.z); wd0[3]=pack2(w00.w,w00.w);
            wd0[4]=pack2(w01.x,w01.x); wd0[5]=pack2(w01.y,w01.y);
            wd0[6]=pack2(w01.z,w01.z); wd0[7]=pack2(w01.w,w01.w);
            wd1[0]=pack2(w10.x,w10.x); wd1[1]=pack2(w10.y,w10.y);
            wd1[2]=pack2(w10.z,w10.z); wd1[3]=pack2(w10.w,w10.w);
            wd1[4]=pack2(w11.x,w11.x); wd1[5]=pack2(w11.y,w11.y);
            wd1[6]=pack2(w11.z,w11.z); wd1[7]=pack2(w11.w,w11.w);
            const ulonglong2* xq2 = xq2base + ii * 128;
            const size_t ibase = (size_t)i * BATCH;   // [i][b] entries
            #pragma unroll
            for (int bp = 0; bp < 4; bp++) {
                const int b2 = b2base + bp;
                u64t a0 = 0, a1 = 0;
                #pragma unroll
                for (int e2 = 0; e2 < 4; e2++) {
                    ulonglong2 xv = xq2[e2 * 32 + b2];
                    a0 = fma2(wd0[2*e2],   xv.x, a0);
                    a0 = fma2(wd0[2*e2+1], xv.y, a0);
                    a1 = fma2(wd1[2*e2],   xv.x, a1);
                    a1 = fma2(wd1[2*e2+1], xv.y, a1);
                }
                float u00,u01,u10,u11;
                unpack2(a0, u00, u01);   // d0   : b_even, b_odd
                unpack2(a1, u10, u11);   // d0+1 : b_even, b_odd
                const int bg = b0 + 2*b2;
                // [i][b][jd]: half2 index = (i*256 + b)*80 + jd2  (128B/line per b)
                uh2[(ibase + bg)     * 80 + jd2] = __floats2half2_rn(u00, u10);
                uh2[(ibase + bg + 1) * 80 + jd2] = __floats2half2_rn(u01, u11);
                s0a[bp] = addf2(s0a[bp], a0);
                s1a[bp] = addf2(s1a[bp], a1);
            }
        }
        #pragma unroll
        for (int bp = 0; bp < 4; bp++) {
            float p0,p1,q0,q1;
            unpack2(s0a[bp], p0, p1);
            unpack2(s1a[bp], q0, q1);
            float* sb = &g_acc[(b0 + 2*(b2base+bp)) * JD + jd2 * 2];
            atomicAdd(sb,           p0);
            atomicAdd(sb + 1,       q0);
            atomicAdd(sb + JD,      p1);
            atomicAdd(sb + JD + 1,  q1);
        }
    }
}

// -------- k_pass: barrier-free warp-gang routing -------------------------
// Warp = 3 b x 10 j on 30 lanes. Softmax sum over j via 4 ring shuffles.
// grid (36 i-chunks, 22 warp-quads), block 128. Zero __syncthreads.
__global__ __launch_bounds__(128, 6) void k_pass(int round) {
    const int wid  = threadIdx.x >> 5;
    const int lane = threadIdx.x & 31;
    const int gw   = blockIdx.y * GW + wid;      // 0..87
    const int jj   = lane - (lane / 10) * 10;    // j (garbage for lanes 30,31)
    const int b    = gw * 3 + lane / 10;
    const bool valid = (lane < 30) && (b < BATCH);
    const int bc   = (b < BATCH) ? b : (BATCH - 1);   // clamped for loads
    const int i0   = blockIdx.x * IT;

    // ring-shuffle source lanes (within the 10-lane j-group)
    const int base = (lane / 10) * 10;
    const int s1 = base + (jj + 1) % 10;
    const int s2 = base + (jj + 2) % 10;
    const int s4 = base + (jj + 4) % 10;
    const int s8 = base + (jj + 8) % 10;

    // ---- vs[jj,:] = v0 (+ v1) — lane-local squash ----
    float vs[DN];
    {
        float tmp[DN]; float sq = 0.f;
        const float* a0 = g_acc + bc * JD + jj * DN;
        #pragma unroll
        for (int d = 0; d < DN; d++) { tmp[d] = 0.1f * a0[d]; sq += tmp[d]*tmp[d]; }
        float sc = (sq / (1.0f + sq)) * rsqrtf(sq + 1e-7f);
        #pragma unroll
        for (int d = 0; d < DN; d++) vs[d] = tmp[d] * sc;
        if (round == 2) {
            const float* a1 = g_acc + BJD + bc * JD + jj * DN;
            sq = 0.f;
            #pragma unroll
            for (int d = 0; d < DN; d++) { tmp[d] = a1[d]; sq += tmp[d]*tmp[d]; }
            sc = (sq / (1.0f + sq)) * rsqrtf(sq + 1e-7f);
            #pragma unroll
            for (int d = 0; d < DN; d++) vs[d] += tmp[d] * sc;
        }
    }

    // lane's u_hat pointer: [i][b][j][d], 32B per entry, warp = 960B dense
    const uint4* up = (const uint4*)(g_uhat
                    + (((size_t)i0 * BATCH + bc) * JN + jj) * DN);
    const size_t istep = (size_t)BATCH * JN * 2;   // uint4 per i (256*160*2B/16B)

    float s[DN];
    #pragma unroll
    for (int d = 0; d < DN; d++) s[d] = 0.f;

    for (int t0 = 0; t0 < IT; t0 += 4) {
        uint4 lo[4], hi[4];
        float ev[4];
        #pragma unroll
        for (int k = 0; k < 4; k++) {
            const uint4* p = up + (size_t)(t0 + k) * istep;
            lo[k] = p[0];
            hi[k] = p[1];
            const __half2* h0 = (const __half2*)&lo[k];
            const __half2* h1 = (const __half2*)&hi[k];
            float a = 0.f;
            #pragma unroll
            for (int d2 = 0; d2 < 4; d2++) {
                float2 f0 = __half22float2(h0[d2]);
                a = fmaf(f0.x, vs[2*d2],     a);
                a = fmaf(f0.y, vs[2*d2 + 1], a);
                float2 f1 = __half22float2(h1[d2]);
                a = fmaf(f1.x, vs[8 + 2*d2], a);
                a = fmaf(f1.y, vs[9 + 2*d2], a);
            }
            ev[k] = fexp(a);
        }
        #pragma unroll
        for (int k = 0; k < 4; k++) {
            // ring reduction over the 10-lane group: distances 1,2,4,+(2@8)
            float e  = ev[k];
            float a1 = e  + __shfl_sync(0xffffffffu, e,  s1);
            float a2 = a1 + __shfl_sync(0xffffffffu, a1, s2);
            float a4 = a2 + __shfl_sync(0xffffffffu, a2, s4);
            float sum = a4 + __shfl_sync(0xffffffffu, a1, s8);
            float c = e * frcp(sum);
            const __half2* h0 = (const __half2*)&lo[k];
            const __half2* h1 = (const __half2*)&hi[k];
            #pragma unroll
            for (int d2 = 0; d2 < 4; d2++) {
                float2 f0 = __half22float2(h0[d2]);
                s[2*d2]     = fmaf(f0.x, c, s[2*d2]);
                s[2*d2 + 1] = fmaf(f0.y, c, s[2*d2 + 1]);
                float2 f1 = __half22float2(h1[d2]);
                s[8 + 2*d2] = fmaf(f1.x, c, s[8 + 2*d2]);
                s[9 + 2*d2] = fmaf(f1.y, c, s[9 + 2*d2]);
            }
        }
    }

    if (valid) {
        float* dst = g_part + (size_t)blockIdx.x * BJD + (size_t)b * JD + jj * DN;
        #pragma unroll
        for (int q = 0; q < 4; q++)
            ((float4*)dst)[q] = make_float4(s[4*q], s[4*q+1], s[4*q+2], s[4*q+3]);
    }
}

// -------- k_reduce: s1 = sum of NP partial slices (float4) ---------------
__global__ void k_reduce() {
    const int idx = blockIdx.x * 256 + threadIdx.x;   // < BJD/4
    const float4* p4 = (const float4*)g_part;
    float4 s = make_float4(0.f, 0.f, 0.f, 0.f);
    #pragma unroll 4
    for (int p = 0; p < NP; p++) {
        float4 v = p4[(size_t)p * (BJD / 4) + idx];
        s.x += v.x; s.y += v.y; s.z += v.z; s.w += v.w;
    }
    ((float4*)g_acc)[BJD / 4 + idx] = s;
}

// -------- k_final: out = squash(sum of partials), float4 -----------------
__global__ __launch_bounds__(256) void k_final(float* __restrict__ out) {
    const int idx = blockIdx.x * 256 + threadIdx.x;   // < BJD/4 (4 jd each)
    const float4* p4 = (const float4*)g_part;
    float4 v = make_float4(0.f, 0.f, 0.f, 0.f);
    #pragma unroll 4
    for (int p = 0; p < NP; p++) {
        float4 t = p4[(size_t)p * (BJD / 4) + idx];
        v.x += t.x; v.y += t.y; v.z += t.z; v.w += t.w;
    }
    float sq = v.x*v.x + v.y*v.y + v.z*v.z + v.w*v.w;
    sq += __shfl_xor_sync(0xffffffff, sq, 1);
    sq += __shfl_xor_sync(0xffffffff, sq, 2);
    float sc = (sq / (1.0f + sq)) * rsqrtf(sq + 1e-7f);
    v.x *= sc; v.y *= sc; v.z *= sc; v.w *= sc;
    ((float4*)out)[idx] = v;
}

// -------- launch --------------------------------------------------------
extern "C" void kernel_launch(void* const* d_in, const int* in_sizes, int n_in,
                              void* d_out, int out_size) {
    const float* x = (const float*)d_in[0];   // [256,1152,8]
    const float* W = (const float*)d_in[1];   // [10,1152,16,8]
    float* out = (float*)d_out;               // [256,10,16]

    void* acc_ptr = nullptr;
    cudaGetSymbolAddress(&acc_ptr, g_acc);
    cudaMemsetAsync(acc_ptr, 0, BJD * sizeof(float));   // s0 only

    k_uhat<<<dim3(ICAPS / 16, BATCH / 64), 320>>>(x, W);
    k_pass<<<dim3(NP, 22), 128>>>(1);
    k_reduce<<<BJD / 4 / 256, 256>>>();
    k_pass<<<dim3(NP, 22), 128>>>(2);
    k_final<<<BJD / 4 / 256, 256>>>(out);
}